// round 17
// baseline (speedup 1.0000x reference)
#include <cuda_runtime.h>
#include <cstdint>
#include <math.h>

// RMAC: x [64, 2048, 16, 16] f32 -> out [64, 14*2048] f32, L2-normalized per batch.
// Regions: L1 1x(16x16), L2 4x(10x10, starts {0,4}), L3 9x(8x8, starts {0,3,6}).
// Two kernels. Main: persistent, cp.async.bulk (1 op / 16KiB tile) + mbarrier
// double-buffer, linear smem + rotated conflict-free LDS reads.

#define B_TOT   64
#define C_TOT   2048
#define NREG    14
#define OUT_PER_B (NREG * C_TOT)        // 28672

#define CHB     16                      // channels per tile
#define TPB     128                     // threads per block
#define TILE_W  (CHB * 256)             // 4096 floats
#define TILE_BYTES (TILE_W * 4)         // 16384
#define NTILES  (B_TOT * (C_TOT / CHB)) // 8192
#define GRID_MAIN 888                   // persistent: 6/SM x 148
#define RSTRIDE 144                     // combine-phase smem stride

__device__ float g_part[NTILES];        // per-tile sum of squares

__device__ __forceinline__ void mbar_init(unsigned mb, unsigned cnt) {
    asm volatile("mbarrier.init.shared.b64 [%0], %1;" :: "r"(mb), "r"(cnt) : "memory");
}
__device__ __forceinline__ void mbar_expect_tx(unsigned mb, unsigned tx) {
    asm volatile("mbarrier.arrive.expect_tx.shared.b64 _, [%0], %1;"
                 :: "r"(mb), "r"(tx) : "memory");
}
__device__ __forceinline__ void bulk_g2s(unsigned dst, const void* src,
                                         unsigned bytes, unsigned mb) {
    asm volatile("cp.async.bulk.shared::cta.global.mbarrier::complete_tx::bytes "
                 "[%0], [%1], %2, [%3];"
                 :: "r"(dst), "l"(src), "r"(bytes), "r"(mb) : "memory");
}
__device__ __forceinline__ void mbar_wait(unsigned mb, unsigned parity) {
    asm volatile(
        "{\n\t.reg .pred P;\n\t"
        "WL_%=:\n\t"
        "mbarrier.try_wait.parity.acquire.cta.shared::cta.b64 P, [%0], %1, 0x989680;\n\t"
        "@P bra.uni WD_%=;\n\t"
        "bra.uni WL_%=;\n\t"
        "WD_%=:\n\t}"
        :: "r"(mb), "r"(parity) : "memory");
}
__device__ __forceinline__ void fence_async() {
    asm volatile("fence.proxy.async.shared::cta;" ::: "memory");
}

__global__ __launch_bounds__(TPB) void rmac_main_kernel(
    const float* __restrict__ x, float* __restrict__ out)
{
    __shared__ __align__(16) float sm[2 * TILE_W];          // 32 KiB double buffer
    __shared__ __align__(8) unsigned long long mbar[2];
    const int t = threadIdx.x;
    const unsigned sb  = (unsigned)__cvta_generic_to_shared(sm);
    const unsigned mb[2] = { (unsigned)__cvta_generic_to_shared(&mbar[0]),
                             (unsigned)__cvta_generic_to_shared(&mbar[1]) };

    if (t == 0) { mbar_init(mb[0], 1); mbar_init(mb[1], 1); }
    fence_async();
    __syncthreads();

    const int t0 = blockIdx.x;
    if (t == 0) {
        // t0 and t0+GRID_MAIN are always < NTILES (887+888 < 8192)
        mbar_expect_tx(mb[0], TILE_BYTES);
        bulk_g2s(sb, x + (size_t)t0 * TILE_W, TILE_BYTES, mb[0]);
        mbar_expect_tx(mb[1], TILE_BYTES);
        bulk_g2s(sb + TILE_BYTES, x + (size_t)(t0 + GRID_MAIN) * TILE_W,
                 TILE_BYTES, mb[1]);
    }

    const int ch     = t & (CHB - 1);   // warp lanes -> 16 channels x 2 row-chunks
    const int rchunk = t >> 4;          // 0..7 -> rows 2*rchunk, 2*rchunk+1
    const int h0     = rchunk * 2;

    int j = 0;
    for (int tile = t0; tile < NTILES; tile += GRID_MAIN, j++) {
        const int s = j & 1;
        float* cur = sm + s * TILE_W;
        const float4* __restrict__ cv = reinterpret_cast<const float4*>(cur) + ch * 64;

        mbar_wait(mb[s], (j >> 1) & 1);   // tile j landed (j+1 still in flight)

        // ---- pool rows h0, h0+1 of channel ch; rotated reads => conflict-free ----
        float rv[32];
        #pragma unroll
        for (int m = 0; m < 8; m++) {
            const int mm = (m + ch) & 7;                  // rotation kills conflicts
            const float4 v = cv[h0 * 4 + mm];             // LDS.128, linear layout
            rv[mm*4+0] = v.x; rv[mm*4+1] = v.y;
            rv[mm*4+2] = v.z; rv[mm*4+3] = v.w;
        }

        float acc[NREG];
        #pragma unroll
        for (int r = 0; r < NREG; r++) acc[r] = 0.0f;

        #pragma unroll
        for (int rr = 0; rr < 2; rr++) {
            const int h = h0 + rr;
            const float* rowv = rv + rr * 16;

            float pre[17];
            pre[0] = 0.0f;
            float p = 0.0f;
            #pragma unroll
            for (int q = 0; q < 16; q++) { p += rowv[q]; pre[q + 1] = p; }

            const float s16  = pre[16];
            const float c10a = pre[10];
            const float c10b = pre[14] - pre[4];
            const float c8a  = pre[8];
            const float c8b  = pre[11] - pre[3];
            const float c8c  = pre[14] - pre[6];

            acc[0] += s16;
            if (h < 10)           { acc[1]  += c10a; acc[2]  += c10b; }
            if (h >= 4 && h < 14) { acc[3]  += c10a; acc[4]  += c10b; }
            if (h < 8)            { acc[5]  += c8a;  acc[6]  += c8b;  acc[7]  += c8c; }
            if (h >= 3 && h < 11) { acc[8]  += c8a;  acc[9]  += c8b;  acc[10] += c8c; }
            if (h >= 6 && h < 14) { acc[11] += c8a;  acc[12] += c8b;  acc[13] += c8c; }
        }
        __syncthreads();     // everyone done reading cur before reusing as scratch

        // ---- combine 8 row-chunk partials per channel via smem (reuse cur) ----
        float* red = cur;                       // 14 * 144 = 2016 floats
        #pragma unroll
        for (int r = 0; r < NREG; r++) red[r * RSTRIDE + t] = acc[r];
        __syncthreads();

        const int b  = tile >> 7;               // 128 tiles per batch
        const int c0 = (tile & 127) * CHB;
        float* __restrict__ outb = out + (size_t)b * OUT_PER_B;
        float ss = 0.0f;
        #pragma unroll
        for (int idx = t; idx < NREG * CHB; idx += TPB) {   // 224 outputs
            const int r  = idx >> 4;
            const int cc = idx & 15;
            float v = 0.0f;
            #pragma unroll
            for (int k = 0; k < 8; k++) v += red[r * RSTRIDE + cc + 16 * k];
            const float inv_area = (r == 0) ? (1.0f / 256.0f)
                                  : (r < 5) ? (1.0f / 100.0f)
                                            : (1.0f / 64.0f);
            v *= inv_area;
            outb[r * C_TOT + c0 + cc] = v;
            ss += v * v;
        }

        // block-reduce ss -> g_part[tile] (plain store, no atomics)
        #pragma unroll
        for (int o = 16; o > 0; o >>= 1)
            ss += __shfl_down_sync(0xffffffffu, ss, o);
        float* wsum = cur + 2048;               // beyond red area
        if ((t & 31) == 0) wsum[t >> 5] = ss;
        __syncthreads();
        if (t == 0) g_part[tile] = wsum[0] + wsum[1] + wsum[2] + wsum[3];
        __syncthreads();     // cur fully consumed -> safe to refill

        const int nt = tile + 2 * GRID_MAIN;
        if (nt < NTILES && t == 0) {
            fence_async();   // order generic smem writes before async overwrite
            mbar_expect_tx(mb[s], TILE_BYTES);
            bulk_g2s(sb + (unsigned)s * TILE_BYTES,
                     x + (size_t)nt * TILE_W, TILE_BYTES, mb[s]);
        }
    }
}

// 448 blocks. Load-first overlap: output loads issued before the partial reduce.
__global__ __launch_bounds__(256) void rmac_norm_kernel(float* __restrict__ out) {
    const int b = blockIdx.y;
    const int s = blockIdx.x;       // 0..6
    const int t = threadIdx.x;

    float4* __restrict__ p =
        reinterpret_cast<float4*>(out + (size_t)b * OUT_PER_B) + s * 1024 + t;

    float4 v[4];
    #pragma unroll
    for (int k = 0; k < 4; k++) v[k] = p[k * 256];

    __shared__ float sinv;
    if (t < 32) {
        float w = g_part[b * 128 + t]      + g_part[b * 128 + t + 32]
                + g_part[b * 128 + t + 64] + g_part[b * 128 + t + 96];
        #pragma unroll
        for (int o = 16; o > 0; o >>= 1)
            w += __shfl_down_sync(0xffffffffu, w, o);
        if (t == 0) sinv = 1.0f / fmaxf(sqrtf(w), 1e-12f);
    }
    __syncthreads();
    const float inv = sinv;

    #pragma unroll
    for (int k = 0; k < 4; k++) {
        v[k].x *= inv; v[k].y *= inv; v[k].z *= inv; v[k].w *= inv;
        p[k * 256] = v[k];
    }
}

extern "C" void kernel_launch(void* const* d_in, const int* in_sizes, int n_in,
                              void* d_out, int out_size) {
    (void)in_sizes; (void)n_in; (void)out_size;
    const float* x = (const float*)d_in[0];
    float* out = (float*)d_out;

    rmac_main_kernel<<<GRID_MAIN, TPB>>>(x, out);

    dim3 gn(OUT_PER_B / (256 * 4 * 4), B_TOT);   // (7, 64) = 448 blocks
    rmac_norm_kernel<<<gn, 256>>>(out);
}